// round 4
// baseline (speedup 1.0000x reference)
#include <cuda_runtime.h>

// Fixed shapes: I(16,3,512,512), T(16,256), P(3,16), Q(16,3)
#define BS        16
#define CHANS     3
#define HW        (512 * 512)        // 262144 elems per channel
#define NCH       (BS * CHANS)       // 48 channel slabs
#define PARTS     64                 // partial sums per channel
#define CHUNK     (HW / PARTS)       // 4096 floats per block
#define NBLOCKS   (NCH * PARTS)      // 3072
#define THREADS   256
#define KDIM      16

// Deterministic scratch: fixed write slots, no float atomics.
__device__ float        g_partials[NBLOCKS];
__device__ unsigned int g_arrived;   // zero-initialized; last block resets it

__global__ __launch_bounds__(THREADS)
void dncm_fused_kernel(const float* __restrict__ I,
                       const float* __restrict__ T,
                       const float* __restrict__ P,
                       const float* __restrict__ Q,
                       float* __restrict__ out) {
    const int bid  = blockIdx.x;          // 0 .. NBLOCKS-1
    const int ch   = bid >> 6;            // / PARTS
    const int part = bid & (PARTS - 1);
    const int t    = threadIdx.x;

    // ---------------- Phase 1: per-block reduction of a 16KB chunk ----------------
    {
        const float4* __restrict__ base =
            reinterpret_cast<const float4*>(I + (size_t)ch * HW + (size_t)part * CHUNK);

        // 1024 float4 / 256 threads -> 4 independent vector loads (MLP=4)
        float4 a = base[t];
        float4 b = base[t + 256];
        float4 c = base[t + 512];
        float4 d = base[t + 768];

        float s = ((a.x + a.y) + (a.z + a.w))
                + ((b.x + b.y) + (b.z + b.w))
                + ((c.x + c.y) + (c.z + c.w))
                + ((d.x + d.y) + (d.z + d.w));

        #pragma unroll
        for (int off = 16; off > 0; off >>= 1)
            s += __shfl_xor_sync(0xffffffffu, s, off);

        __shared__ float smem[THREADS / 32];
        if ((t & 31) == 0) smem[t >> 5] = s;
        __syncthreads();

        if (t == 0) {
            float tot = 0.0f;
            #pragma unroll
            for (int i = 0; i < THREADS / 32; i++) tot += smem[i];
            g_partials[bid] = tot;   // fixed slot -> deterministic
        }
    }

    // ---------------- Arrival protocol: last block does the epilogue ----------------
    __shared__ unsigned int is_last;
    __threadfence();                 // make partial visible before signalling
    if (t == 0) {
        unsigned int old = atomicAdd(&g_arrived, 1u);
        is_last = (old == (unsigned int)(NBLOCKS - 1)) ? 1u : 0u;
    }
    __syncthreads();
    if (!is_last) return;

    __threadfence();                 // acquire: all partials now visible

    // ---------------- Phase 2 (one block): reduce partials -> S[48] ----------------
    // Threads 0..191: (ch2, quarter) teams of 4 lanes, 16 loads each (independent).
    __shared__ float S[NCH];
    if (t < 192) {
        const int ch2 = t >> 2;
        const int q4  = t & 3;
        const float* __restrict__ p = g_partials + ch2 * PARTS + q4 * 16;
        float v = 0.0f;
        #pragma unroll
        for (int i = 0; i < 16; i++) v += p[i];
        v += __shfl_xor_sync(0xffffffffu, v, 1);
        v += __shfl_xor_sync(0xffffffffu, v, 2);
        if (q4 == 0) S[ch2] = v;
    }
    __syncthreads();

    // ---------------- Phase 3: tiny matrix math, thread (b,k) ----------------
    {
        const int b = t >> 4;            // 0..15
        const int k = t & 15;            // 0..15

        // r[j] = sum_c Q[j,c]  (uniform broadcast loads, L1-hit)
        float r[KDIM];
        #pragma unroll
        for (int j = 0; j < KDIM; j++)
            r[j] = Q[j * 3 + 0] + Q[j * 3 + 1] + Q[j * 3 + 2];

        const float4* __restrict__ Tv =
            reinterpret_cast<const float4*>(T + b * (KDIM * KDIM) + k * KDIM);
        float4 t0 = Tv[0], t1 = Tv[1], t2 = Tv[2], t3 = Tv[3];

        // A[b,k] = sum_c S[b,c] * P[c,k]
        const float A = S[b * CHANS + 0] * P[0 * KDIM + k]
                      + S[b * CHANS + 1] * P[1 * KDIM + k]
                      + S[b * CHANS + 2] * P[2 * KDIM + k];

        // d = T_b[k,:] . r
        float d = t0.x * r[0]  + t0.y * r[1]  + t0.z * r[2]  + t0.w * r[3]
                + t1.x * r[4]  + t1.y * r[5]  + t1.z * r[6]  + t1.w * r[7]
                + t2.x * r[8]  + t2.y * r[9]  + t2.z * r[10] + t2.w * r[11]
                + t3.x * r[12] + t3.y * r[13] + t3.z * r[14] + t3.w * r[15];

        float val = d * A;
        #pragma unroll
        for (int off = 8; off > 0; off >>= 1)
            val += __shfl_xor_sync(0xffffffffu, val, off);

        if (k == 0)
            out[b] = val * (1.0f / (float)(HW * CHANS));
    }

    // Reset the counter for the next launch / graph replay.
    __syncthreads();
    if (t == 0) g_arrived = 0u;
}

extern "C" void kernel_launch(void* const* d_in, const int* in_sizes, int n_in,
                              void* d_out, int out_size) {
    const float* I = (const float*)d_in[0];   // (16,3,512,512)
    const float* T = (const float*)d_in[1];   // (16,256)
    const float* P = (const float*)d_in[2];   // (3,16)
    const float* Q = (const float*)d_in[3];   // (16,3)
    float* out = (float*)d_out;               // (16,1)

    dncm_fused_kernel<<<NBLOCKS, THREADS>>>(I, T, P, Q, out);
}

// round 5
// speedup vs baseline: 1.0216x; 1.0216x over previous
#include <cuda_runtime.h>

// Fixed shapes: I(16,3,512,512), T(16,256), P(3,16), Q(16,3)
#define BS        16
#define CHANS     3
#define HW        (512 * 512)        // 262144 elems per channel
#define NCH       (BS * CHANS)       // 48 channel slabs
#define PARTS     64                 // partial sums per channel
#define CHUNK     (HW / PARTS)       // 4096 floats per block
#define NBLOCKS   (NCH * PARTS)      // 3072
#define THREADS   256
#define KDIM      16

// Deterministic scratch: fixed write slots, no float atomics.
__device__ float        g_partials[NBLOCKS];
__device__ unsigned int g_arrived;   // zero-initialized; last block resets it

// Release-acquire arrival signal: orders this block's partial store before the
// signal, and (for the winner) makes all other blocks' partials visible.
// Crucially this does NOT emit CCTL.IVALL (no L1 flush), unlike __threadfence().
__device__ __forceinline__ unsigned int arrive_acq_rel(unsigned int* ctr) {
    unsigned int old;
    asm volatile("atom.acq_rel.gpu.global.add.u32 %0, [%1], 1;"
                 : "=r"(old) : "l"(ctr) : "memory");
    return old;
}

__global__ __launch_bounds__(THREADS)
void dncm_fused_kernel(const float* __restrict__ I,
                       const float* __restrict__ T,
                       const float* __restrict__ P,
                       const float* __restrict__ Q,
                       float* __restrict__ out) {
    const int bid  = blockIdx.x;          // 0 .. NBLOCKS-1
    const int ch   = bid >> 6;            // / PARTS
    const int part = bid & (PARTS - 1);
    const int t    = threadIdx.x;

    // ---------------- Phase 1: per-block reduction of a 16KB chunk ----------------
    {
        const float4* __restrict__ base =
            reinterpret_cast<const float4*>(I + (size_t)ch * HW + (size_t)part * CHUNK);

        // 1024 float4 / 256 threads -> 4 independent vector loads (MLP=4)
        float4 a = base[t];
        float4 b = base[t + 256];
        float4 c = base[t + 512];
        float4 d = base[t + 768];

        float s = ((a.x + a.y) + (a.z + a.w))
                + ((b.x + b.y) + (b.z + b.w))
                + ((c.x + c.y) + (c.z + c.w))
                + ((d.x + d.y) + (d.z + d.w));

        #pragma unroll
        for (int off = 16; off > 0; off >>= 1)
            s += __shfl_xor_sync(0xffffffffu, s, off);

        __shared__ float smem[THREADS / 32];
        if ((t & 31) == 0) smem[t >> 5] = s;
        __syncthreads();

        if (t == 0) {
            float tot = 0.0f;
            #pragma unroll
            for (int i = 0; i < THREADS / 32; i++) tot += smem[i];
            g_partials[bid] = tot;   // fixed slot -> deterministic
        }
    }

    // -------- Arrival: last block does the epilogue (release/acquire, no L1 flush) --------
    __shared__ unsigned int is_last;
    __syncthreads();                 // partial STG issued before thread 0 signals
    if (t == 0) {
        unsigned int old = arrive_acq_rel(&g_arrived);
        is_last = (old == (unsigned int)(NBLOCKS - 1)) ? 1u : 0u;
    }
    __syncthreads();
    if (!is_last) return;

    // ---------------- Phase 2 (one block): reduce partials -> S[48] ----------------
    // Threads 0..191: (ch2, quarter) teams of 4 lanes, 16 L2 loads each (independent).
    __shared__ float S[NCH];
    if (t < 192) {
        const int ch2 = t >> 2;
        const int q4  = t & 3;
        const float* p = g_partials + ch2 * PARTS + q4 * 16;
        float v = 0.0f;
        #pragma unroll
        for (int i = 0; i < 16; i++) v += __ldcg(p + i);   // L2 path: skip stale L1
        v += __shfl_xor_sync(0xffffffffu, v, 1);
        v += __shfl_xor_sync(0xffffffffu, v, 2);
        if (q4 == 0) S[ch2] = v;
    }
    __syncthreads();

    // ---------------- Phase 3: tiny matrix math, thread (b,k) ----------------
    {
        const int b = t >> 4;            // 0..15
        const int k = t & 15;            // 0..15

        // r[j] = sum_c Q[j,c]  (uniform broadcast loads)
        float r[KDIM];
        #pragma unroll
        for (int j = 0; j < KDIM; j++)
            r[j] = Q[j * 3 + 0] + Q[j * 3 + 1] + Q[j * 3 + 2];

        const float4* __restrict__ Tv =
            reinterpret_cast<const float4*>(T + b * (KDIM * KDIM) + k * KDIM);
        float4 t0 = Tv[0], t1 = Tv[1], t2 = Tv[2], t3 = Tv[3];

        // A[b,k] = sum_c S[b,c] * P[c,k]
        const float A = S[b * CHANS + 0] * P[0 * KDIM + k]
                      + S[b * CHANS + 1] * P[1 * KDIM + k]
                      + S[b * CHANS + 2] * P[2 * KDIM + k];

        // d = T_b[k,:] . r
        float d = t0.x * r[0]  + t0.y * r[1]  + t0.z * r[2]  + t0.w * r[3]
                + t1.x * r[4]  + t1.y * r[5]  + t1.z * r[6]  + t1.w * r[7]
                + t2.x * r[8]  + t2.y * r[9]  + t2.z * r[10] + t2.w * r[11]
                + t3.x * r[12] + t3.y * r[13] + t3.z * r[14] + t3.w * r[15];

        float val = d * A;
        #pragma unroll
        for (int off = 8; off > 0; off >>= 1)
            val += __shfl_xor_sync(0xffffffffu, val, off);

        if (k == 0)
            out[b] = val * (1.0f / (float)(HW * CHANS));
    }

    // Reset the counter for the next launch / graph replay.
    __syncthreads();
    if (t == 0) atomicExch(&g_arrived, 0u);
}

extern "C" void kernel_launch(void* const* d_in, const int* in_sizes, int n_in,
                              void* d_out, int out_size) {
    const float* I = (const float*)d_in[0];   // (16,3,512,512)
    const float* T = (const float*)d_in[1];   // (16,256)
    const float* P = (const float*)d_in[2];   // (3,16)
    const float* Q = (const float*)d_in[3];   // (16,3)
    float* out = (float*)d_out;               // (16,1)

    dncm_fused_kernel<<<NBLOCKS, THREADS>>>(I, T, P, Q, out);
}

// round 6
// speedup vs baseline: 1.2391x; 1.2128x over previous
#include <cuda_runtime.h>

// Fixed shapes: I(16,3,512,512), T(16,256), P(3,16), Q(16,3)
#define BS        16
#define CHANS     3
#define HW        (512 * 512)        // 262144 elems per channel
#define NCH       (BS * CHANS)       // 48 channel slabs
#define PARTS     64                 // partial sums per channel
#define CHUNK     (HW / PARTS)       // 4096 floats per block
#define NBLOCKS   (NCH * PARTS)      // 3072
#define THREADS   256
#define KDIM      16

// Deterministic scratch: fixed write slots, no atomics.
__device__ float g_partials[NBLOCKS];

__global__ __launch_bounds__(THREADS)
void dncm_reduce_kernel(const float* __restrict__ I) {
    const int bid  = blockIdx.x;          // 0 .. NBLOCKS-1
    const int ch   = bid >> 6;            // / PARTS
    const int part = bid & (PARTS - 1);

    const float4* __restrict__ base =
        reinterpret_cast<const float4*>(I + (size_t)ch * HW + (size_t)part * CHUNK);

    const int t = threadIdx.x;
    // 1024 float4 / 256 threads -> 4 independent vector loads (MLP=4)
    float4 a = base[t];
    float4 b = base[t + 256];
    float4 c = base[t + 512];
    float4 d = base[t + 768];

    float s = ((a.x + a.y) + (a.z + a.w))
            + ((b.x + b.y) + (b.z + b.w))
            + ((c.x + c.y) + (c.z + c.w))
            + ((d.x + d.y) + (d.z + d.w));

    #pragma unroll
    for (int off = 16; off > 0; off >>= 1)
        s += __shfl_xor_sync(0xffffffffu, s, off);

    __shared__ float smem[THREADS / 32];
    if ((t & 31) == 0) smem[t >> 5] = s;
    __syncthreads();

    if (t == 0) {
        float tot = 0.0f;
        #pragma unroll
        for (int i = 0; i < THREADS / 32; i++) tot += smem[i];
        g_partials[bid] = tot;   // fixed slot -> deterministic

        // Release the programmatically-dependent epilogue kernel early.
        cudaTriggerProgrammaticLaunchCompletion();
    }
}

// Epilogue (PDL secondary): prefetch T/Q/P (not written by kernel 1) BEFORE
// gridDepSync, then consume the partials. 768 threads = 48 teams x 16 lanes.
__global__ __launch_bounds__(768)
void dncm_final_kernel(const float* __restrict__ T,
                       const float* __restrict__ P,
                       const float* __restrict__ Q,
                       float* __restrict__ out) {
    const int t  = threadIdx.x;        // 0..767
    const int ch = t >> 4;             // 0..47
    const int j  = t & 15;             // lane within team

    // ---- Prefetch phase (overlaps with primary kernel's tail) ----
    const int b = t >> 4;              // batch (valid for t < 256)
    const int k = t & 15;              // k index
    float4 t0, t1, t2, t3;
    float r[KDIM];
    float P0 = 0.f, P1 = 0.f, P2 = 0.f;
    if (t < 256) {
        const float4* __restrict__ Tv =
            reinterpret_cast<const float4*>(T + b * (KDIM * KDIM) + k * KDIM);
        t0 = Tv[0]; t1 = Tv[1]; t2 = Tv[2]; t3 = Tv[3];
        #pragma unroll
        for (int q = 0; q < KDIM; q++)
            r[q] = Q[q * 3 + 0] + Q[q * 3 + 1] + Q[q * 3 + 2];
        P0 = P[0 * KDIM + k];
        P1 = P[1 * KDIM + k];
        P2 = P[2 * KDIM + k];
    }

    // ---- Wait for the primary grid's memory to be visible ----
    cudaGridDependencySynchronize();

    // ---- Reduce partials: 16-lane teams, 4 independent loads each ----
    const float* __restrict__ p = g_partials + ch * PARTS;
    float s = (p[j] + p[j + 16]) + (p[j + 32] + p[j + 48]);
    #pragma unroll
    for (int off = 8; off > 0; off >>= 1)
        s += __shfl_xor_sync(0xffffffffu, s, off);

    __shared__ float S[NCH];
    if (j == 0) S[ch] = s;
    __syncthreads();

    if (t < 256) {
        // A[b,k] = sum_c S[b,c] * P[c,k]
        const float A = S[b * CHANS + 0] * P0
                      + S[b * CHANS + 1] * P1
                      + S[b * CHANS + 2] * P2;

        // d = T_b[k,:] . r
        float d = t0.x * r[0]  + t0.y * r[1]  + t0.z * r[2]  + t0.w * r[3]
                + t1.x * r[4]  + t1.y * r[5]  + t1.z * r[6]  + t1.w * r[7]
                + t2.x * r[8]  + t2.y * r[9]  + t2.z * r[10] + t2.w * r[11]
                + t3.x * r[12] + t3.y * r[13] + t3.z * r[14] + t3.w * r[15];

        float val = d * A;
        #pragma unroll
        for (int off = 8; off > 0; off >>= 1)
            val += __shfl_xor_sync(0xffffffffu, val, off);

        if (k == 0)
            out[b] = val * (1.0f / (float)(HW * CHANS));
    }
}

extern "C" void kernel_launch(void* const* d_in, const int* in_sizes, int n_in,
                              void* d_out, int out_size) {
    const float* I = (const float*)d_in[0];   // (16,3,512,512)
    const float* T = (const float*)d_in[1];   // (16,256)
    const float* P = (const float*)d_in[2];   // (3,16)
    const float* Q = (const float*)d_in[3];   // (16,3)
    float* out = (float*)d_out;               // (16,1)

    dncm_reduce_kernel<<<NBLOCKS, THREADS>>>(I);

    // Launch epilogue with Programmatic Dependent Launch so it overlaps the
    // primary kernel's tail; correctness is enforced by gridDepSync inside.
    cudaLaunchConfig_t cfg = {};
    cfg.gridDim  = dim3(1, 1, 1);
    cfg.blockDim = dim3(768, 1, 1);
    cfg.dynamicSmemBytes = 0;
    cfg.stream = 0;   // legacy default stream (same as <<<>>> above)
    cudaLaunchAttribute attr[1];
    attr[0].id = cudaLaunchAttributeProgrammaticStreamSerialization;
    attr[0].val.programmaticStreamSerializationAllowed = 1;
    cfg.attrs = attr;
    cfg.numAttrs = 1;
    cudaLaunchKernelEx(&cfg, dncm_final_kernel, T, P, Q, out);
}

// round 7
// speedup vs baseline: 1.2649x; 1.0208x over previous
#include <cuda_runtime.h>

// Fixed shapes: I(16,3,512,512), T(16,256), P(3,16), Q(16,3)
#define BS        16
#define CHANS     3
#define HW        (512 * 512)        // 262144 floats per channel
#define NCH       (BS * CHANS)       // 48 channel slabs
#define PARTS     16                 // partials per channel
#define NBLOCKS   (NCH * PARTS)      // 768 blocks -> single wave on 148 SMs
#define THREADS   256
#define VPT       16                 // float4 per thread (2 batches of 8)
#define CHUNK4    (THREADS * VPT)    // 4096 float4 = 16384 floats per block
#define KDIM      16

// Deterministic scratch: fixed write slots, no atomics.
__device__ float g_partials[NBLOCKS];

__global__ __launch_bounds__(THREADS)
void dncm_reduce_kernel(const float* __restrict__ I) {
    const int bid  = blockIdx.x;          // 0 .. 767
    const int ch   = bid >> 4;            // / PARTS
    const int part = bid & (PARTS - 1);
    const int t    = threadIdx.x;

    const float4* __restrict__ base =
        reinterpret_cast<const float4*>(I + (size_t)ch * HW) + (size_t)part * CHUNK4;

    float s = 0.0f;
    // Two batches of 8 independent float4 loads (MLP=8, front-batched per batch)
    #pragma unroll
    for (int batch = 0; batch < 2; batch++) {
        float4 v[8];
        #pragma unroll
        for (int i = 0; i < 8; i++)
            v[i] = base[batch * (8 * THREADS) + i * THREADS + t];
        float b0 = 0.f, b1 = 0.f;
        #pragma unroll
        for (int i = 0; i < 8; i += 2) {
            b0 += (v[i].x + v[i].y) + (v[i].z + v[i].w);
            b1 += (v[i+1].x + v[i+1].y) + (v[i+1].z + v[i+1].w);
        }
        s += b0 + b1;
    }

    #pragma unroll
    for (int off = 16; off > 0; off >>= 1)
        s += __shfl_xor_sync(0xffffffffu, s, off);

    __shared__ float smem[THREADS / 32];
    if ((t & 31) == 0) smem[t >> 5] = s;
    __syncthreads();

    if (t == 0) {
        float tot = 0.0f;
        #pragma unroll
        for (int i = 0; i < THREADS / 32; i++) tot += smem[i];
        g_partials[bid] = tot;   // fixed slot -> deterministic

        // Release the programmatically-dependent epilogue early.
        cudaTriggerProgrammaticLaunchCompletion();
    }
}

// Epilogue (PDL secondary): prefetch T/Q/P before gridDepSync, then consume
// the 768 partials. 768 threads = 48 teams x 16 lanes (1 partial per lane).
__global__ __launch_bounds__(768)
void dncm_final_kernel(const float* __restrict__ T,
                       const float* __restrict__ P,
                       const float* __restrict__ Q,
                       float* __restrict__ out) {
    const int t  = threadIdx.x;        // 0..767
    const int ch = t >> 4;             // 0..47
    const int j  = t & 15;             // lane within team

    // ---- Prefetch phase (overlaps with primary tail) ----
    const int b = t >> 4;              // batch (valid for t < 256)
    const int k = t & 15;              // k index
    float4 t0, t1, t2, t3;
    float r[KDIM];
    float P0 = 0.f, P1 = 0.f, P2 = 0.f;
    if (t < 256) {
        const float4* __restrict__ Tv =
            reinterpret_cast<const float4*>(T + b * (KDIM * KDIM) + k * KDIM);
        t0 = Tv[0]; t1 = Tv[1]; t2 = Tv[2]; t3 = Tv[3];
        #pragma unroll
        for (int q = 0; q < KDIM; q++)
            r[q] = Q[q * 3 + 0] + Q[q * 3 + 1] + Q[q * 3 + 2];
        P0 = P[0 * KDIM + k];
        P1 = P[1 * KDIM + k];
        P2 = P[2 * KDIM + k];
    }

    // ---- Wait for the primary grid's memory to be visible ----
    cudaGridDependencySynchronize();

    // ---- Reduce partials: 16 lanes per channel, 1 load each ----
    float s = g_partials[ch * PARTS + j];
    #pragma unroll
    for (int off = 8; off > 0; off >>= 1)
        s += __shfl_xor_sync(0xffffffffu, s, off);

    __shared__ float S[NCH];
    if (j == 0) S[ch] = s;
    __syncthreads();

    if (t < 256) {
        // A[b,k] = sum_c S[b,c] * P[c,k]
        const float A = S[b * CHANS + 0] * P0
                      + S[b * CHANS + 1] * P1
                      + S[b * CHANS + 2] * P2;

        // d = T_b[k,:] . r
        float d = t0.x * r[0]  + t0.y * r[1]  + t0.z * r[2]  + t0.w * r[3]
                + t1.x * r[4]  + t1.y * r[5]  + t1.z * r[6]  + t1.w * r[7]
                + t2.x * r[8]  + t2.y * r[9]  + t2.z * r[10] + t2.w * r[11]
                + t3.x * r[12] + t3.y * r[13] + t3.z * r[14] + t3.w * r[15];

        float val = d * A;
        #pragma unroll
        for (int off = 8; off > 0; off >>= 1)
            val += __shfl_xor_sync(0xffffffffu, val, off);

        if (k == 0)
            out[b] = val * (1.0f / (float)(HW * CHANS));
    }
}

extern "C" void kernel_launch(void* const* d_in, const int* in_sizes, int n_in,
                              void* d_out, int out_size) {
    const float* I = (const float*)d_in[0];   // (16,3,512,512)
    const float* T = (const float*)d_in[1];   // (16,256)
    const float* P = (const float*)d_in[2];   // (3,16)
    const float* Q = (const float*)d_in[3];   // (16,3)
    float* out = (float*)d_out;               // (16,1)

    dncm_reduce_kernel<<<NBLOCKS, THREADS>>>(I);

    cudaLaunchConfig_t cfg = {};
    cfg.gridDim  = dim3(1, 1, 1);
    cfg.blockDim = dim3(768, 1, 1);
    cfg.dynamicSmemBytes = 0;
    cfg.stream = 0;
    cudaLaunchAttribute attr[1];
    attr[0].id = cudaLaunchAttributeProgrammaticStreamSerialization;
    attr[0].val.programmaticStreamSerializationAllowed = 1;
    cfg.attrs = attr;
    cfg.numAttrs = 1;
    cudaLaunchKernelEx(&cfg, dncm_final_kernel, T, P, Q, out);
}